// round 13
// baseline (speedup 1.0000x reference)
#include <cuda_runtime.h>
#include <math.h>
#include <stdint.h>

#define Bsz 256
#define Cc 3
#define IMGSZ 32
#define Pp 4
#define Dd 256
#define Hh 8
#define HDIM 32
#define T1 65
#define MLP_HID 2048
#define HEAD_HID 8192
#define NCLS 10
#define PATCH_DIM 48
#define MROWS (Bsz * T1)   // 16640

// GEMM tiling
#define BM 128
#define BKK 32
#define ASTRIDE 36   // 32 + 4 pad (floats)
#define GEMM_SMEM_BYTES_N(TBN) ((2*BM*ASTRIDE + 2*BKK*((TBN)+8)) * 4)

// ---------------- scratch (allocation-free: __device__ globals) ----------------
__device__ float g_tok[Bsz * T1 * Dd];
__device__ float g_h[Bsz * T1 * Dd];
__device__ float g_qkv[Bsz * T1 * 3 * Dd];
__device__ float g_r[Bsz * T1 * Dd];
__device__ float g_m[Bsz * T1 * MLP_HID];
__device__ float g_hidden[Bsz * HEAD_HID];
__device__ float g_stats[2 * Bsz];

// ---------------- PTX helpers ----------------
__device__ __forceinline__ void cp16(uint32_t s, const void* g) {
    asm volatile("cp.async.cg.shared.global [%0], [%1], 16;\n" :: "r"(s), "l"(g));
}
__device__ __forceinline__ void cp_commit() {
    asm volatile("cp.async.commit_group;\n");
}
template<int N>
__device__ __forceinline__ void cp_wait() {
    asm volatile("cp.async.wait_group %0;\n" :: "n"(N));
}
__device__ __forceinline__ uint32_t f2tf32(float f) {
    uint32_t o;
    asm("cvt.rna.tf32.f32 %0, %1;" : "=r"(o) : "f"(f));
    return o;
}
__device__ __forceinline__ void ldsm_x4(uint32_t& r0, uint32_t& r1, uint32_t& r2, uint32_t& r3, uint32_t addr) {
    asm volatile("ldmatrix.sync.aligned.m8n8.x4.shared.b16 {%0,%1,%2,%3}, [%4];"
                 : "=r"(r0), "=r"(r1), "=r"(r2), "=r"(r3) : "r"(addr));
}
__device__ __forceinline__ void mma_tf32(float c[4], uint32_t a0, uint32_t a1, uint32_t a2, uint32_t a3,
                                         uint32_t b0, uint32_t b1) {
    asm volatile("mma.sync.aligned.m16n8k8.row.col.f32.tf32.tf32.f32 "
                 "{%0,%1,%2,%3}, {%4,%5,%6,%7}, {%8,%9}, {%0,%1,%2,%3};"
                 : "+f"(c[0]), "+f"(c[1]), "+f"(c[2]), "+f"(c[3])
                 : "r"(a0), "r"(a1), "r"(a2), "r"(a3), "r"(b0), "r"(b1));
}

// ---------------- patch embed + cls + positional encoding ----------------
__global__ void patch_embed_kernel(const float* __restrict__ x,
                                   const float* __restrict__ cls,
                                   const float* __restrict__ Wp,
                                   const float* __restrict__ bp,
                                   float* __restrict__ out)
{
    int bt = blockIdx.x;
    int b = bt / T1, tt = bt % T1;
    int d = threadIdx.x;
    __shared__ float sp[PATCH_DIM];
    float val;
    if (tt == 0) {
        val = cls[d];
    } else {
        int pi = (tt - 1) >> 3, pj = (tt - 1) & 7;
        if (d < PATCH_DIM) {
            int c = d / 16, rem = d % 16, p = rem >> 2, q = rem & 3;
            sp[d] = x[((size_t)(b * Cc + c) * IMGSZ + pi * Pp + p) * IMGSZ + pj * Pp + q];
        }
        __syncthreads();
        float acc = bp[d];
        #pragma unroll
        for (int m = 0; m < PATCH_DIM; m++) acc = fmaf(sp[m], Wp[m * Dd + d], acc);
        val = acc;
    }
    int jj = d >> 1;
    float div = expf(-logf(10000.0f) * (float)(2 * jj) / (float)Dd);
    float ang = (float)tt * div;
    float pe = (d & 1) ? cosf(ang) : sinf(ang);
    out[(size_t)(b * T1 + tt) * Dd + d] = val + pe;
}

// ---------------- LayerNorm: stats (per sample) + apply (fully parallel) ----------------
__global__ void ln_stats_kernel(const float* __restrict__ x, float* __restrict__ stats)
{
    int b = blockIdx.x;
    const float4* xb = (const float4*)(x + (size_t)b * T1 * Dd);
    float s = 0.f, ss = 0.f;
    for (int i = threadIdx.x; i < T1 * Dd / 4; i += blockDim.x) {
        float4 v = xb[i];
        s  += v.x + v.y + v.z + v.w;
        ss += v.x*v.x + v.y*v.y + v.z*v.z + v.w*v.w;
    }
    __shared__ float sh_s[256], sh_ss[256];
    sh_s[threadIdx.x] = s; sh_ss[threadIdx.x] = ss;
    __syncthreads();
    for (int o = 128; o > 0; o >>= 1) {
        if (threadIdx.x < o) {
            sh_s[threadIdx.x]  += sh_s[threadIdx.x + o];
            sh_ss[threadIdx.x] += sh_ss[threadIdx.x + o];
        }
        __syncthreads();
    }
    if (threadIdx.x == 0) {
        float invN = 1.0f / (float)(T1 * Dd);
        float mu = sh_s[0] * invN;
        float var = sh_ss[0] * invN - mu * mu;
        stats[2 * b]     = mu;
        stats[2 * b + 1] = rsqrtf(var + 1e-5f);
    }
}

__global__ void ln_apply_kernel(const float* __restrict__ x,
                                const float* __restrict__ w,
                                const float* __restrict__ bb,
                                const float* __restrict__ stats,
                                float* __restrict__ out)
{
    int idx = blockIdx.x * blockDim.x + threadIdx.x;   // one float4 per thread
    int i4 = idx * 4;
    int b = i4 / (T1 * Dd);
    int j = i4 - b * (T1 * Dd);
    float mu  = stats[2 * b];
    float inv = stats[2 * b + 1];
    float4 xv = *(const float4*)(x + i4);
    float4 wv = *(const float4*)(w + j);
    float4 bv = *(const float4*)(bb + j);
    float4 o;
    o.x = (xv.x - mu) * inv * wv.x + bv.x;
    o.y = (xv.y - mu) * inv * wv.y + bv.y;
    o.z = (xv.z - mu) * inv * wv.z + bv.z;
    o.w = (xv.w - mu) * inv * wv.w + bv.w;
    *(float4*)(out + i4) = o;
}

// ---------------- TF32 tensor-core GEMM: C = act(A@B + bias [+ res]) ----------------
// A (M,K) row-major, B (K,N) row-major. M%128==0, N%TBN==0, K%32==0.
// ACT: 0 none, 1 relu, 2 silu.  TBN in {128, 64}.
// Tiles are rounded to tf32 IN SHARED MEMORY once per element (convert pass),
// so the mainloop issues no cvt instructions at all.
template<int ACT, bool HAS_RES, int TBN>
__global__ __launch_bounds__(256) void gemm_tc(
    const float* __restrict__ A, const float* __restrict__ B,
    const float* __restrict__ bias, const float* __restrict__ res,
    float* __restrict__ C, int M, int N, int K)
{
    constexpr int NT = TBN / 32;       // n-subtiles per warp
    constexpr int BSTR = TBN + 8;
    constexpr int AF4 = BM * ASTRIDE / 4;          // 1152 float4
    constexpr int BF4 = BKK * BSTR / 4;            // 1088 (TBN=128) / 576 (TBN=64)
    constexpr int NCONV = (AF4 + BF4 + 255) / 256;
    extern __shared__ float smem[];
    float* Bs = smem + 2 * BM * ASTRIDE;
    const uint32_t smem_u = (uint32_t)__cvta_generic_to_shared(smem);
    const uint32_t bs_u = smem_u + 2 * BM * ASTRIDE * 4;

    const int tid = threadIdx.x;
    const int lane = tid & 31, wid = tid >> 5;
    const int wm = (wid & 1) * 64;
    const int wn = (wid >> 1) * (TBN / 4);
    const int m0 = blockIdx.y * BM;
    const int n0 = blockIdx.x * TBN;

    float c[4][NT][4];
    #pragma unroll
    for (int i = 0; i < 4; i++)
        #pragma unroll
        for (int j = 0; j < NT; j++)
            #pragma unroll
            for (int r = 0; r < 4; r++) c[i][j][r] = 0.f;

    const int a_row = tid >> 3, a_c4 = (tid & 7) * 4;
    const int KT = K / BKK;

    auto load_tile = [&](int kt, int buf) {
        const float* Ag = A + (size_t)m0 * K + (size_t)kt * BKK;
        #pragma unroll
        for (int i = 0; i < 4; i++) {
            int r = a_row + i * 32;
            cp16(smem_u + (uint32_t)(((buf * BM + r) * ASTRIDE + a_c4) * 4),
                 Ag + (size_t)r * K + a_c4);
        }
        const float* Bg = B + (size_t)kt * BKK * N + n0;
        #pragma unroll
        for (int i = 0; i < NT; i++) {
            int idx = tid + i * 256;
            int r = idx / (TBN / 4), c4 = (idx % (TBN / 4)) * 4;
            cp16(bs_u + (uint32_t)(((buf * BKK + r) * BSTR + c4) * 4),
                 Bg + (size_t)r * N + c4);
        }
        cp_commit();
    };

    // in-place tf32 rounding of one buffer (pads converted harmlessly, never read)
    auto convert_buf = [&](int buf) {
        float4* Ab = (float4*)(smem + buf * BM * ASTRIDE);
        float4* Bb = (float4*)(Bs + buf * BKK * BSTR);
        #pragma unroll
        for (int i = 0; i < NCONV; i++) {
            int idx = tid + i * 256;
            if (idx < AF4) {
                float4 v = Ab[idx];
                uint4 o;
                o.x = f2tf32(v.x); o.y = f2tf32(v.y);
                o.z = f2tf32(v.z); o.w = f2tf32(v.w);
                *(uint4*)(Ab + idx) = o;
            } else if (idx < AF4 + BF4) {
                int bi = idx - AF4;
                float4 v = Bb[bi];
                uint4 o;
                o.x = f2tf32(v.x); o.y = f2tf32(v.y);
                o.z = f2tf32(v.z); o.w = f2tf32(v.w);
                *(uint4*)(Bb + bi) = o;
            }
        }
    };

    load_tile(0, 0);

    int buf = 0;
    for (int kt = 0; kt < KT; kt++) {
        if (kt + 1 < KT) {
            load_tile(kt + 1, buf ^ 1);
            cp_wait<1>();
        } else {
            cp_wait<0>();
        }
        __syncthreads();

        convert_buf(buf);
        __syncthreads();

        const int a_mbase = buf * BM + wm + (lane & 15);
        const int a_koff = (lane >> 4) * 4;
        #pragma unroll
        for (int kk = 0; kk < 4; kk++) {
            uint32_t a[4][4];
            #pragma unroll
            for (int mt = 0; mt < 4; mt++) {
                uint32_t addr = smem_u + (uint32_t)(((a_mbase + mt * 16) * ASTRIDE + kk * 8 + a_koff) * 4);
                ldsm_x4(a[mt][0], a[mt][1], a[mt][2], a[mt][3], addr);
            }
            uint32_t b[NT][2];
            const int kr = buf * BKK + kk * 8 + (lane & 3);
            const int nc = wn + (lane >> 2);
            #pragma unroll
            for (int nt = 0; nt < NT; nt++) {
                b[nt][0] = __float_as_uint(Bs[kr * BSTR + nc + nt * 8]);
                b[nt][1] = __float_as_uint(Bs[(kr + 4) * BSTR + nc + nt * 8]);
            }
            #pragma unroll
            for (int mt = 0; mt < 4; mt++)
                #pragma unroll
                for (int nt = 0; nt < NT; nt++)
                    mma_tf32(c[mt][nt], a[mt][0], a[mt][1], a[mt][2], a[mt][3],
                             b[nt][0], b[nt][1]);
        }
        __syncthreads();
        buf ^= 1;
    }

    #pragma unroll
    for (int mt = 0; mt < 4; mt++) {
        #pragma unroll
        for (int nt = 0; nt < NT; nt++) {
            int m = m0 + wm + mt * 16 + (lane >> 2);
            int n = n0 + wn + nt * 8 + (lane & 3) * 2;
            #pragma unroll
            for (int half = 0; half < 2; half++) {
                int mm = m + half * 8;
                float v0 = c[mt][nt][half * 2 + 0] + bias[n];
                float v1 = c[mt][nt][half * 2 + 1] + bias[n + 1];
                if (HAS_RES) {
                    v0 += res[(size_t)mm * N + n];
                    v1 += res[(size_t)mm * N + n + 1];
                }
                if (ACT == 1) { v0 = fmaxf(v0, 0.f); v1 = fmaxf(v1, 0.f); }
                else if (ACT == 2) {
                    v0 = v0 / (1.0f + __expf(-v0));
                    v1 = v1 / (1.0f + __expf(-v1));
                }
                float2 o = make_float2(v0, v1);
                *(float2*)&C[(size_t)mm * N + n] = o;
            }
        }
    }
}

// ---------------- fused attention per (b, h): register-tiled ----------------
#define QSTR 36   // HDIM + 4 pad, breaks bank alignment of rows
__global__ __launch_bounds__(256) void attn_kernel(const float* __restrict__ qkv,
                                                   const float* __restrict__ resid,
                                                   float* __restrict__ out)
{
    int bh = blockIdx.x;
    int b = bh / Hh, h = bh % Hh;
    int tid = threadIdx.x;
    int lane = tid & 31, wid = tid >> 5;
    __shared__ float q[T1][QSTR], k[T1][QSTR], v[T1][QSTR];
    __shared__ float sc[T1][T1 + 1];

    const float* base = qkv + (size_t)b * T1 * 3 * Dd + h * 3 * HDIM;
    for (int idx = tid; idx < T1 * 8; idx += 256) {
        int t = idx >> 3, d4 = (idx & 7) * 4;
        const float* p = base + (size_t)t * 3 * Dd;
        *(float4*)&q[t][d4] = *(const float4*)(p + d4);
        *(float4*)&k[t][d4] = *(const float4*)(p + HDIM + d4);
        *(float4*)&v[t][d4] = *(const float4*)(p + 2 * HDIM + d4);
    }
    __syncthreads();

    const float scale = rsqrtf((float)HDIM);

    // ---- score phase: 4x8 output tile per thread (153 active threads) ----
    if (tid < 153) {
        int tr = tid / 9, tc = tid % 9;       // tr<17, tc<9
        int r0 = tr * 4, c0 = tc * 8;
        float acc[4][8];
        #pragma unroll
        for (int i = 0; i < 4; i++)
            #pragma unroll
            for (int j = 0; j < 8; j++) acc[i][j] = 0.f;
        #pragma unroll
        for (int d4 = 0; d4 < 8; d4++) {
            float4 qv[4];
            #pragma unroll
            for (int i = 0; i < 4; i++) {
                int r = r0 + i; r = r < 64 ? r : 64;
                qv[i] = *(const float4*)&q[r][d4 * 4];
            }
            float4 kv[8];
            #pragma unroll
            for (int j = 0; j < 8; j++) {
                int c = c0 + j; c = c < 64 ? c : 64;
                kv[j] = *(const float4*)&k[c][d4 * 4];
            }
            #pragma unroll
            for (int i = 0; i < 4; i++)
                #pragma unroll
                for (int j = 0; j < 8; j++) {
                    acc[i][j] = fmaf(qv[i].x, kv[j].x, acc[i][j]);
                    acc[i][j] = fmaf(qv[i].y, kv[j].y, acc[i][j]);
                    acc[i][j] = fmaf(qv[i].z, kv[j].z, acc[i][j]);
                    acc[i][j] = fmaf(qv[i].w, kv[j].w, acc[i][j]);
                }
        }
        #pragma unroll
        for (int i = 0; i < 4; i++) {
            int r = r0 + i;
            if (r < T1)
                #pragma unroll
                for (int j = 0; j < 8; j++) {
                    int c = c0 + j;
                    if (c < T1) sc[r][c] = acc[i][j] * scale;
                }
        }
    }
    __syncthreads();

    // ---- softmax: warp per row ----
    for (int r = wid; r < T1; r += 8) {
        float mx = -1e30f;
        for (int cc = lane; cc < T1; cc += 32) mx = fmaxf(mx, sc[r][cc]);
        #pragma unroll
        for (int o = 16; o > 0; o >>= 1) mx = fmaxf(mx, __shfl_xor_sync(0xffffffffu, mx, o));
        float sum = 0.f;
        for (int cc = lane; cc < T1; cc += 32) {
            float e = __expf(sc[r][cc] - mx);
            sc[r][cc] = e; sum += e;
        }
        #pragma unroll
        for (int o = 16; o > 0; o >>= 1) sum += __shfl_xor_sync(0xffffffffu, sum, o);
        float inv = 1.0f / sum;
        for (int cc = lane; cc < T1; cc += 32) sc[r][cc] *= inv;
    }
    __syncthreads();

    // ---- AV phase: 4x4 output tile per thread (136 active threads) ----
    if (tid < 136) {
        int tr = tid >> 3, tc = tid & 7;      // tr<17, tc<8
        int r0 = tr * 4, c0 = tc * 4;
        float acc[4][4];
        #pragma unroll
        for (int i = 0; i < 4; i++)
            #pragma unroll
            for (int j = 0; j < 4; j++) acc[i][j] = 0.f;
        for (int cc = 0; cc < T1; cc++) {
            float4 vv = *(const float4*)&v[cc][c0];
            #pragma unroll
            for (int i = 0; i < 4; i++) {
                int r = r0 + i; r = r < 64 ? r : 64;
                float s = sc[r][cc];
                acc[i][0] = fmaf(s, vv.x, acc[i][0]);
                acc[i][1] = fmaf(s, vv.y, acc[i][1]);
                acc[i][2] = fmaf(s, vv.z, acc[i][2]);
                acc[i][3] = fmaf(s, vv.w, acc[i][3]);
            }
        }
        #pragma unroll
        for (int i = 0; i < 4; i++) {
            int r = r0 + i;
            if (r < T1) {
                size_t o = (size_t)(b * T1 + r) * Dd + h * HDIM + c0;
                float4 rr = *(const float4*)(resid + o);
                float4 ov;
                ov.x = acc[i][0] + rr.x;
                ov.y = acc[i][1] + rr.y;
                ov.z = acc[i][2] + rr.z;
                ov.w = acc[i][3] + rr.w;
                *(float4*)(out + o) = ov;
            }
        }
    }
}

// ---------------- head2: (B, 8192) @ (8192, 10) + bias ----------------
__global__ void head2_kernel(const float* __restrict__ hidden,
                             const float* __restrict__ w,
                             const float* __restrict__ bias,
                             float* __restrict__ out)
{
    int b = blockIdx.x;
    const float* hb = hidden + (size_t)b * HEAD_HID;
    float s[NCLS];
    #pragma unroll
    for (int c = 0; c < NCLS; c++) s[c] = 0.f;
    for (int kk = threadIdx.x; kk < HEAD_HID; kk += 256) {
        float hv = hb[kk];
        const float* wr = w + (size_t)kk * NCLS;
        #pragma unroll
        for (int c = 0; c < NCLS; c++) s[c] = fmaf(hv, wr[c], s[c]);
    }
    __shared__ float red[256];
    #pragma unroll
    for (int c = 0; c < NCLS; c++) {
        red[threadIdx.x] = s[c];
        __syncthreads();
        for (int o = 128; o > 0; o >>= 1) {
            if (threadIdx.x < o) red[threadIdx.x] += red[threadIdx.x + o];
            __syncthreads();
        }
        if (threadIdx.x == 0) out[b * NCLS + c] = red[0] + bias[c];
        __syncthreads();
    }
}

// ---------------- launch ----------------
extern "C" void kernel_launch(void* const* d_in, const int* in_sizes, int n_in,
                              void* d_out, int out_size)
{
    const float* x       = (const float*)d_in[0];
    const float* cls     = (const float*)d_in[1];
    const float* Wp      = (const float*)d_in[2];
    const float* bp      = (const float*)d_in[3];
    const float* qkv_w   = (const float*)d_in[4];
    const float* qkv_b   = (const float*)d_in[5];
    const float* ln_w    = (const float*)d_in[6];
    const float* ln_b    = (const float*)d_in[7];
    const float* mlp1_w  = (const float*)d_in[8];
    const float* mlp1_b  = (const float*)d_in[9];
    const float* mlp2_w  = (const float*)d_in[10];
    const float* mlp2_b  = (const float*)d_in[11];
    const float* head1_w = (const float*)d_in[12];
    const float* head1_b = (const float*)d_in[13];
    const float* head2_w = (const float*)d_in[14];
    const float* head2_b = (const float*)d_in[15];
    float* outp = (float*)d_out;

    float *tok, *h, *qkv, *r, *m, *hidden, *stats;
    cudaGetSymbolAddress((void**)&tok,    g_tok);
    cudaGetSymbolAddress((void**)&h,      g_h);
    cudaGetSymbolAddress((void**)&qkv,    g_qkv);
    cudaGetSymbolAddress((void**)&r,      g_r);
    cudaGetSymbolAddress((void**)&m,      g_m);
    cudaGetSymbolAddress((void**)&hidden, g_hidden);
    cudaGetSymbolAddress((void**)&stats,  g_stats);

    const int SM128 = GEMM_SMEM_BYTES_N(128);
    const int SM64  = GEMM_SMEM_BYTES_N(64);
    cudaFuncSetAttribute(gemm_tc<0,false,128>, cudaFuncAttributeMaxDynamicSharedMemorySize, SM128);
    cudaFuncSetAttribute(gemm_tc<1,false,128>, cudaFuncAttributeMaxDynamicSharedMemorySize, SM128);
    cudaFuncSetAttribute(gemm_tc<0,true ,64 >, cudaFuncAttributeMaxDynamicSharedMemorySize, SM64);
    cudaFuncSetAttribute(gemm_tc<2,false,64 >, cudaFuncAttributeMaxDynamicSharedMemorySize, SM64);

    // 1. patch embed + cls + pe
    patch_embed_kernel<<<Bsz * T1, 256>>>(x, cls, Wp, bp, tok);

    const int LN_APPLY_GRID = MROWS * Dd / 4 / 256;   // 4160

    // 2. two transformer layers
    for (int i = 0; i < 2; i++) {
        const float* lw  = ln_w   + (size_t)i * T1 * Dd;
        const float* lb  = ln_b   + (size_t)i * T1 * Dd;
        const float* qw  = qkv_w  + (size_t)i * Dd * 3 * Dd;
        const float* qb  = qkv_b  + (size_t)i * 3 * Dd;
        const float* w1  = mlp1_w + (size_t)i * Dd * MLP_HID;
        const float* b1  = mlp1_b + (size_t)i * MLP_HID;
        const float* w2  = mlp2_w + (size_t)i * MLP_HID * Dd;
        const float* b2  = mlp2_b + (size_t)i * Dd;

        ln_stats_kernel<<<Bsz, 256>>>(tok, stats);
        ln_apply_kernel<<<LN_APPLY_GRID, 256>>>(tok, lw, lb, stats, h);

        dim3 gq(3 * Dd / 128, MROWS / BM);
        gemm_tc<0,false,128><<<gq, 256, SM128>>>(h, qw, qb, nullptr, qkv, MROWS, 3 * Dd, Dd);

        attn_kernel<<<Bsz * Hh, 256>>>(qkv, tok, r);

        ln_stats_kernel<<<Bsz, 256>>>(r, stats);
        ln_apply_kernel<<<LN_APPLY_GRID, 256>>>(r, lw, lb, stats, h);

        dim3 g1(MLP_HID / 128, MROWS / BM);
        gemm_tc<1,false,128><<<g1, 256, SM128>>>(h, w1, b1, nullptr, m, MROWS, MLP_HID, Dd);

        dim3 g2(Dd / 64, MROWS / BM);   // 520 blocks
        gemm_tc<0,true,64><<<g2, 256, SM64>>>(m, w2, b2, r, tok, MROWS, Dd, MLP_HID);
    }

    // 3. head1: (256, 16640) @ (16640, 8192), silu — 256 blocks
    dim3 gh(HEAD_HID / 64, Bsz / BM);
    gemm_tc<2,false,64><<<gh, 256, SM64>>>(tok, head1_w, head1_b, nullptr, hidden,
                                           Bsz, HEAD_HID, T1 * Dd);

    // 4. head2: (256, 8192) @ (8192, 10)
    head2_kernel<<<Bsz, 256>>>(hidden, head2_w, head2_b, outp);
}

// round 14
// speedup vs baseline: 1.3187x; 1.3187x over previous
#include <cuda_runtime.h>
#include <math.h>
#include <stdint.h>

#define Bsz 256
#define Cc 3
#define IMGSZ 32
#define Pp 4
#define Dd 256
#define Hh 8
#define HDIM 32
#define T1 65
#define MLP_HID 2048
#define HEAD_HID 8192
#define NCLS 10
#define PATCH_DIM 48
#define MROWS (Bsz * T1)   // 16640

// GEMM tiling
#define BM 128
#define BKK 32
#define ASTRIDE 36   // 32 + 4 pad (floats)
#define GEMM_SMEM_BYTES_N(TBN) ((2*BM*ASTRIDE + 2*BKK*((TBN)+8)) * 4)

// ---------------- scratch (allocation-free: __device__ globals) ----------------
__device__ float g_tok[Bsz * T1 * Dd];
__device__ float g_h[Bsz * T1 * Dd];
__device__ float g_qkv[Bsz * T1 * 3 * Dd];
__device__ float g_r[Bsz * T1 * Dd];
__device__ float g_m[Bsz * T1 * MLP_HID];
__device__ float g_hidden[Bsz * HEAD_HID];
__device__ float g_stats[2 * Bsz];

// ---------------- PTX helpers ----------------
__device__ __forceinline__ void cp16(uint32_t s, const void* g) {
    asm volatile("cp.async.cg.shared.global [%0], [%1], 16;\n" :: "r"(s), "l"(g));
}
__device__ __forceinline__ void cp_commit() {
    asm volatile("cp.async.commit_group;\n");
}
template<int N>
__device__ __forceinline__ void cp_wait() {
    asm volatile("cp.async.wait_group %0;\n" :: "n"(N));
}
__device__ __forceinline__ uint32_t f2tf32(float f) {
    uint32_t o;
    asm("cvt.rna.tf32.f32 %0, %1;" : "=r"(o) : "f"(f));
    return o;
}
__device__ __forceinline__ float roundtf(float f) {
    return __uint_as_float(f2tf32(f));
}
__device__ __forceinline__ void ldsm_x4(uint32_t& r0, uint32_t& r1, uint32_t& r2, uint32_t& r3, uint32_t addr) {
    asm volatile("ldmatrix.sync.aligned.m8n8.x4.shared.b16 {%0,%1,%2,%3}, [%4];"
                 : "=r"(r0), "=r"(r1), "=r"(r2), "=r"(r3) : "r"(addr));
}
__device__ __forceinline__ void mma_tf32(float c[4], uint32_t a0, uint32_t a1, uint32_t a2, uint32_t a3,
                                         uint32_t b0, uint32_t b1) {
    asm volatile("mma.sync.aligned.m16n8k8.row.col.f32.tf32.tf32.f32 "
                 "{%0,%1,%2,%3}, {%4,%5,%6,%7}, {%8,%9}, {%0,%1,%2,%3};"
                 : "+f"(c[0]), "+f"(c[1]), "+f"(c[2]), "+f"(c[3])
                 : "r"(a0), "r"(a1), "r"(a2), "r"(a3), "r"(b0), "r"(b1));
}

// ---------------- patch embed + cls + positional encoding ----------------
__global__ void patch_embed_kernel(const float* __restrict__ x,
                                   const float* __restrict__ cls,
                                   const float* __restrict__ Wp,
                                   const float* __restrict__ bp,
                                   float* __restrict__ out)
{
    int bt = blockIdx.x;
    int b = bt / T1, tt = bt % T1;
    int d = threadIdx.x;
    __shared__ float sp[PATCH_DIM];
    float val;
    if (tt == 0) {
        val = cls[d];
    } else {
        int pi = (tt - 1) >> 3, pj = (tt - 1) & 7;
        if (d < PATCH_DIM) {
            int c = d / 16, rem = d % 16, p = rem >> 2, q = rem & 3;
            sp[d] = x[((size_t)(b * Cc + c) * IMGSZ + pi * Pp + p) * IMGSZ + pj * Pp + q];
        }
        __syncthreads();
        float acc = bp[d];
        #pragma unroll
        for (int m = 0; m < PATCH_DIM; m++) acc = fmaf(sp[m], Wp[m * Dd + d], acc);
        val = acc;
    }
    int jj = d >> 1;
    float div = expf(-logf(10000.0f) * (float)(2 * jj) / (float)Dd);
    float ang = (float)tt * div;
    float pe = (d & 1) ? cosf(ang) : sinf(ang);
    out[(size_t)(b * T1 + tt) * Dd + d] = val + pe;
}

// ---------------- LayerNorm: stats (per sample) + apply (fully parallel) ----------------
__global__ void ln_stats_kernel(const float* __restrict__ x, float* __restrict__ stats)
{
    int b = blockIdx.x;
    const float4* xb = (const float4*)(x + (size_t)b * T1 * Dd);
    float s = 0.f, ss = 0.f;
    for (int i = threadIdx.x; i < T1 * Dd / 4; i += blockDim.x) {
        float4 v = xb[i];
        s  += v.x + v.y + v.z + v.w;
        ss += v.x*v.x + v.y*v.y + v.z*v.z + v.w*v.w;
    }
    __shared__ float sh_s[256], sh_ss[256];
    sh_s[threadIdx.x] = s; sh_ss[threadIdx.x] = ss;
    __syncthreads();
    for (int o = 128; o > 0; o >>= 1) {
        if (threadIdx.x < o) {
            sh_s[threadIdx.x]  += sh_s[threadIdx.x + o];
            sh_ss[threadIdx.x] += sh_ss[threadIdx.x + o];
        }
        __syncthreads();
    }
    if (threadIdx.x == 0) {
        float invN = 1.0f / (float)(T1 * Dd);
        float mu = sh_s[0] * invN;
        float var = sh_ss[0] * invN - mu * mu;
        stats[2 * b]     = mu;
        stats[2 * b + 1] = rsqrtf(var + 1e-5f);
    }
}

// output is pre-rounded to tf32 (h feeds GEMM A operands only)
__global__ void ln_apply_kernel(const float* __restrict__ x,
                                const float* __restrict__ w,
                                const float* __restrict__ bb,
                                const float* __restrict__ stats,
                                float* __restrict__ out)
{
    int idx = blockIdx.x * blockDim.x + threadIdx.x;   // one float4 per thread
    int i4 = idx * 4;
    int b = i4 / (T1 * Dd);
    int j = i4 - b * (T1 * Dd);
    float mu  = stats[2 * b];
    float inv = stats[2 * b + 1];
    float4 xv = *(const float4*)(x + i4);
    float4 wv = *(const float4*)(w + j);
    float4 bv = *(const float4*)(bb + j);
    float4 o;
    o.x = roundtf((xv.x - mu) * inv * wv.x + bv.x);
    o.y = roundtf((xv.y - mu) * inv * wv.y + bv.y);
    o.z = roundtf((xv.z - mu) * inv * wv.z + bv.z);
    o.w = roundtf((xv.w - mu) * inv * wv.w + bv.w);
    *(float4*)(out + i4) = o;
}

// elementwise tf32 rounding (tok -> h before head1)
__global__ void round_kernel(const float* __restrict__ x, float* __restrict__ out)
{
    int idx = blockIdx.x * blockDim.x + threadIdx.x;
    int i4 = idx * 4;
    float4 v = *(const float4*)(x + i4);
    float4 o;
    o.x = roundtf(v.x); o.y = roundtf(v.y);
    o.z = roundtf(v.z); o.w = roundtf(v.w);
    *(float4*)(out + i4) = o;
}

// ---------------- TF32 tensor-core GEMM: C = act(A@B + bias [+ res]) ----------------
// A (M,K) row-major (values MUST be pre-rounded to tf32 by the producer),
// B (K,N) row-major (rounded in registers here). M%128==0, N%TBN==0, K%32==0.
// ACT: 0 none, 1 relu, 2 silu.  TBN in {128, 64}.
// ROUND_OUT: round output to tf32 (when C feeds another GEMM's A operand).
template<int ACT, bool HAS_RES, int TBN, bool ROUND_OUT>
__global__ __launch_bounds__(256) void gemm_tc(
    const float* __restrict__ A, const float* __restrict__ B,
    const float* __restrict__ bias, const float* __restrict__ res,
    float* __restrict__ C, int M, int N, int K)
{
    constexpr int NT = TBN / 32;       // n-subtiles per warp
    constexpr int BSTR = TBN + 8;
    extern __shared__ float smem[];
    float* Bs = smem + 2 * BM * ASTRIDE;
    const uint32_t smem_u = (uint32_t)__cvta_generic_to_shared(smem);
    const uint32_t bs_u = smem_u + 2 * BM * ASTRIDE * 4;

    const int tid = threadIdx.x;
    const int lane = tid & 31, wid = tid >> 5;
    const int wm = (wid & 1) * 64;
    const int wn = (wid >> 1) * (TBN / 4);
    const int m0 = blockIdx.y * BM;
    const int n0 = blockIdx.x * TBN;

    float c[4][NT][4];
    #pragma unroll
    for (int i = 0; i < 4; i++)
        #pragma unroll
        for (int j = 0; j < NT; j++)
            #pragma unroll
            for (int r = 0; r < 4; r++) c[i][j][r] = 0.f;

    const int a_row = tid >> 3, a_c4 = (tid & 7) * 4;
    const int KT = K / BKK;

    auto load_tile = [&](int kt, int buf) {
        const float* Ag = A + (size_t)m0 * K + (size_t)kt * BKK;
        #pragma unroll
        for (int i = 0; i < 4; i++) {
            int r = a_row + i * 32;
            cp16(smem_u + (uint32_t)(((buf * BM + r) * ASTRIDE + a_c4) * 4),
                 Ag + (size_t)r * K + a_c4);
        }
        const float* Bg = B + (size_t)kt * BKK * N + n0;
        #pragma unroll
        for (int i = 0; i < NT; i++) {
            int idx = tid + i * 256;
            int r = idx / (TBN / 4), c4 = (idx % (TBN / 4)) * 4;
            cp16(bs_u + (uint32_t)(((buf * BKK + r) * BSTR + c4) * 4),
                 Bg + (size_t)r * N + c4);
        }
        cp_commit();
    };

    load_tile(0, 0);

    int buf = 0;
    for (int kt = 0; kt < KT; kt++) {
        if (kt + 1 < KT) {
            load_tile(kt + 1, buf ^ 1);
            cp_wait<1>();
        } else {
            cp_wait<0>();
        }
        __syncthreads();

        const int a_mbase = buf * BM + wm + (lane & 15);
        const int a_koff = (lane >> 4) * 4;
        #pragma unroll
        for (int kk = 0; kk < 4; kk++) {
            // A fragments: pre-rounded tf32 bits, use directly (no cvt)
            uint32_t a[4][4];
            #pragma unroll
            for (int mt = 0; mt < 4; mt++) {
                uint32_t addr = smem_u + (uint32_t)(((a_mbase + mt * 16) * ASTRIDE + kk * 8 + a_koff) * 4);
                ldsm_x4(a[mt][0], a[mt][1], a[mt][2], a[mt][3], addr);
            }
            // B fragments: cvt in registers (once per warp)
            uint32_t b[NT][2];
            const int kr = buf * BKK + kk * 8 + (lane & 3);
            const int nc = wn + (lane >> 2);
            #pragma unroll
            for (int nt = 0; nt < NT; nt++) {
                b[nt][0] = f2tf32(Bs[kr * BSTR + nc + nt * 8]);
                b[nt][1] = f2tf32(Bs[(kr + 4) * BSTR + nc + nt * 8]);
            }
            #pragma unroll
            for (int mt = 0; mt < 4; mt++)
                #pragma unroll
                for (int nt = 0; nt < NT; nt++)
                    mma_tf32(c[mt][nt], a[mt][0], a[mt][1], a[mt][2], a[mt][3],
                             b[nt][0], b[nt][1]);
        }
        __syncthreads();
        buf ^= 1;
    }

    #pragma unroll
    for (int mt = 0; mt < 4; mt++) {
        #pragma unroll
        for (int nt = 0; nt < NT; nt++) {
            int m = m0 + wm + mt * 16 + (lane >> 2);
            int n = n0 + wn + nt * 8 + (lane & 3) * 2;
            #pragma unroll
            for (int half = 0; half < 2; half++) {
                int mm = m + half * 8;
                float v0 = c[mt][nt][half * 2 + 0] + bias[n];
                float v1 = c[mt][nt][half * 2 + 1] + bias[n + 1];
                if (HAS_RES) {
                    v0 += res[(size_t)mm * N + n];
                    v1 += res[(size_t)mm * N + n + 1];
                }
                if (ACT == 1) { v0 = fmaxf(v0, 0.f); v1 = fmaxf(v1, 0.f); }
                else if (ACT == 2) {
                    v0 = v0 / (1.0f + __expf(-v0));
                    v1 = v1 / (1.0f + __expf(-v1));
                }
                if (ROUND_OUT) { v0 = roundtf(v0); v1 = roundtf(v1); }
                float2 o = make_float2(v0, v1);
                *(float2*)&C[(size_t)mm * N + n] = o;
            }
        }
    }
}

// ---------------- fused attention per (b, h): register-tiled ----------------
#define QSTR 36   // HDIM + 4 pad, breaks bank alignment of rows
__global__ __launch_bounds__(256) void attn_kernel(const float* __restrict__ qkv,
                                                   const float* __restrict__ resid,
                                                   float* __restrict__ out)
{
    int bh = blockIdx.x;
    int b = bh / Hh, h = bh % Hh;
    int tid = threadIdx.x;
    int lane = tid & 31, wid = tid >> 5;
    __shared__ float q[T1][QSTR], k[T1][QSTR], v[T1][QSTR];
    __shared__ float sc[T1][T1 + 1];

    const float* base = qkv + (size_t)b * T1 * 3 * Dd + h * 3 * HDIM;
    for (int idx = tid; idx < T1 * 8; idx += 256) {
        int t = idx >> 3, d4 = (idx & 7) * 4;
        const float* p = base + (size_t)t * 3 * Dd;
        *(float4*)&q[t][d4] = *(const float4*)(p + d4);
        *(float4*)&k[t][d4] = *(const float4*)(p + HDIM + d4);
        *(float4*)&v[t][d4] = *(const float4*)(p + 2 * HDIM + d4);
    }
    __syncthreads();

    const float scale = rsqrtf((float)HDIM);

    // ---- score phase: 4x8 output tile per thread (153 active threads) ----
    if (tid < 153) {
        int tr = tid / 9, tc = tid % 9;       // tr<17, tc<9
        int r0 = tr * 4, c0 = tc * 8;
        float acc[4][8];
        #pragma unroll
        for (int i = 0; i < 4; i++)
            #pragma unroll
            for (int j = 0; j < 8; j++) acc[i][j] = 0.f;
        #pragma unroll
        for (int d4 = 0; d4 < 8; d4++) {
            float4 qv[4];
            #pragma unroll
            for (int i = 0; i < 4; i++) {
                int r = r0 + i; r = r < 64 ? r : 64;
                qv[i] = *(const float4*)&q[r][d4 * 4];
            }
            float4 kv[8];
            #pragma unroll
            for (int j = 0; j < 8; j++) {
                int c = c0 + j; c = c < 64 ? c : 64;
                kv[j] = *(const float4*)&k[c][d4 * 4];
            }
            #pragma unroll
            for (int i = 0; i < 4; i++)
                #pragma unroll
                for (int j = 0; j < 8; j++) {
                    acc[i][j] = fmaf(qv[i].x, kv[j].x, acc[i][j]);
                    acc[i][j] = fmaf(qv[i].y, kv[j].y, acc[i][j]);
                    acc[i][j] = fmaf(qv[i].z, kv[j].z, acc[i][j]);
                    acc[i][j] = fmaf(qv[i].w, kv[j].w, acc[i][j]);
                }
        }
        #pragma unroll
        for (int i = 0; i < 4; i++) {
            int r = r0 + i;
            if (r < T1)
                #pragma unroll
                for (int j = 0; j < 8; j++) {
                    int c = c0 + j;
                    if (c < T1) sc[r][c] = acc[i][j] * scale;
                }
        }
    }
    __syncthreads();

    // ---- softmax: warp per row ----
    for (int r = wid; r < T1; r += 8) {
        float mx = -1e30f;
        for (int cc = lane; cc < T1; cc += 32) mx = fmaxf(mx, sc[r][cc]);
        #pragma unroll
        for (int o = 16; o > 0; o >>= 1) mx = fmaxf(mx, __shfl_xor_sync(0xffffffffu, mx, o));
        float sum = 0.f;
        for (int cc = lane; cc < T1; cc += 32) {
            float e = __expf(sc[r][cc] - mx);
            sc[r][cc] = e; sum += e;
        }
        #pragma unroll
        for (int o = 16; o > 0; o >>= 1) sum += __shfl_xor_sync(0xffffffffu, sum, o);
        float inv = 1.0f / sum;
        for (int cc = lane; cc < T1; cc += 32) sc[r][cc] *= inv;
    }
    __syncthreads();

    // ---- AV phase: 4x4 output tile per thread (136 active threads) ----
    if (tid < 136) {
        int tr = tid >> 3, tc = tid & 7;      // tr<17, tc<8
        int r0 = tr * 4, c0 = tc * 4;
        float acc[4][4];
        #pragma unroll
        for (int i = 0; i < 4; i++)
            #pragma unroll
            for (int j = 0; j < 4; j++) acc[i][j] = 0.f;
        for (int cc = 0; cc < T1; cc++) {
            float4 vv = *(const float4*)&v[cc][c0];
            #pragma unroll
            for (int i = 0; i < 4; i++) {
                int r = r0 + i; r = r < 64 ? r : 64;
                float s = sc[r][cc];
                acc[i][0] = fmaf(s, vv.x, acc[i][0]);
                acc[i][1] = fmaf(s, vv.y, acc[i][1]);
                acc[i][2] = fmaf(s, vv.z, acc[i][2]);
                acc[i][3] = fmaf(s, vv.w, acc[i][3]);
            }
        }
        #pragma unroll
        for (int i = 0; i < 4; i++) {
            int r = r0 + i;
            if (r < T1) {
                size_t o = (size_t)(b * T1 + r) * Dd + h * HDIM + c0;
                float4 rr = *(const float4*)(resid + o);
                float4 ov;
                ov.x = acc[i][0] + rr.x;
                ov.y = acc[i][1] + rr.y;
                ov.z = acc[i][2] + rr.z;
                ov.w = acc[i][3] + rr.w;
                *(float4*)(out + o) = ov;
            }
        }
    }
}

// ---------------- head2: (B, 8192) @ (8192, 10) + bias ----------------
__global__ void head2_kernel(const float* __restrict__ hidden,
                             const float* __restrict__ w,
                             const float* __restrict__ bias,
                             float* __restrict__ out)
{
    int b = blockIdx.x;
    const float* hb = hidden + (size_t)b * HEAD_HID;
    float s[NCLS];
    #pragma unroll
    for (int c = 0; c < NCLS; c++) s[c] = 0.f;
    for (int kk = threadIdx.x; kk < HEAD_HID; kk += 256) {
        float hv = hb[kk];
        const float* wr = w + (size_t)kk * NCLS;
        #pragma unroll
        for (int c = 0; c < NCLS; c++) s[c] = fmaf(hv, wr[c], s[c]);
    }
    __shared__ float red[256];
    #pragma unroll
    for (int c = 0; c < NCLS; c++) {
        red[threadIdx.x] = s[c];
        __syncthreads();
        for (int o = 128; o > 0; o >>= 1) {
            if (threadIdx.x < o) red[threadIdx.x] += red[threadIdx.x + o];
            __syncthreads();
        }
        if (threadIdx.x == 0) out[b * NCLS + c] = red[0] + bias[c];
        __syncthreads();
    }
}

// ---------------- launch ----------------
extern "C" void kernel_launch(void* const* d_in, const int* in_sizes, int n_in,
                              void* d_out, int out_size)
{
    const float* x       = (const float*)d_in[0];
    const float* cls     = (const float*)d_in[1];
    const float* Wp      = (const float*)d_in[2];
    const float* bp      = (const float*)d_in[3];
    const float* qkv_w   = (const float*)d_in[4];
    const float* qkv_b   = (const float*)d_in[5];
    const float* ln_w    = (const float*)d_in[6];
    const float* ln_b    = (const float*)d_in[7];
    const float* mlp1_w  = (const float*)d_in[8];
    const float* mlp1_b  = (const float*)d_in[9];
    const float* mlp2_w  = (const float*)d_in[10];
    const float* mlp2_b  = (const float*)d_in[11];
    const float* head1_w = (const float*)d_in[12];
    const float* head1_b = (const float*)d_in[13];
    const float* head2_w = (const float*)d_in[14];
    const float* head2_b = (const float*)d_in[15];
    float* outp = (float*)d_out;

    float *tok, *h, *qkv, *r, *m, *hidden, *stats;
    cudaGetSymbolAddress((void**)&tok,    g_tok);
    cudaGetSymbolAddress((void**)&h,      g_h);
    cudaGetSymbolAddress((void**)&qkv,    g_qkv);
    cudaGetSymbolAddress((void**)&r,      g_r);
    cudaGetSymbolAddress((void**)&m,      g_m);
    cudaGetSymbolAddress((void**)&hidden, g_hidden);
    cudaGetSymbolAddress((void**)&stats,  g_stats);

    const int SM128 = GEMM_SMEM_BYTES_N(128);
    const int SM64  = GEMM_SMEM_BYTES_N(64);
    cudaFuncSetAttribute(gemm_tc<0,false,128,false>, cudaFuncAttributeMaxDynamicSharedMemorySize, SM128);
    cudaFuncSetAttribute(gemm_tc<1,false,128,true >, cudaFuncAttributeMaxDynamicSharedMemorySize, SM128);
    cudaFuncSetAttribute(gemm_tc<0,true ,64 ,false>, cudaFuncAttributeMaxDynamicSharedMemorySize, SM64);
    cudaFuncSetAttribute(gemm_tc<2,false,64 ,false>, cudaFuncAttributeMaxDynamicSharedMemorySize, SM64);

    // 1. patch embed + cls + pe
    patch_embed_kernel<<<Bsz * T1, 256>>>(x, cls, Wp, bp, tok);

    const int EW_GRID = MROWS * Dd / 4 / 256;   // 4160

    // 2. two transformer layers
    for (int i = 0; i < 2; i++) {
        const float* lw  = ln_w   + (size_t)i * T1 * Dd;
        const float* lb  = ln_b   + (size_t)i * T1 * Dd;
        const float* qw  = qkv_w  + (size_t)i * Dd * 3 * Dd;
        const float* qb  = qkv_b  + (size_t)i * 3 * Dd;
        const float* w1  = mlp1_w + (size_t)i * Dd * MLP_HID;
        const float* b1  = mlp1_b + (size_t)i * MLP_HID;
        const float* w2  = mlp2_w + (size_t)i * MLP_HID * Dd;
        const float* b2  = mlp2_b + (size_t)i * Dd;

        ln_stats_kernel<<<Bsz, 256>>>(tok, stats);
        ln_apply_kernel<<<EW_GRID, 256>>>(tok, lw, lb, stats, h);   // h pre-rounded

        dim3 gq(3 * Dd / 128, MROWS / BM);
        gemm_tc<0,false,128,false><<<gq, 256, SM128>>>(h, qw, qb, nullptr, qkv, MROWS, 3 * Dd, Dd);

        attn_kernel<<<Bsz * Hh, 256>>>(qkv, tok, r);

        ln_stats_kernel<<<Bsz, 256>>>(r, stats);
        ln_apply_kernel<<<EW_GRID, 256>>>(r, lw, lb, stats, h);     // h pre-rounded

        dim3 g1(MLP_HID / 128, MROWS / BM);
        gemm_tc<1,false,128,true><<<g1, 256, SM128>>>(h, w1, b1, nullptr, m, MROWS, MLP_HID, Dd);  // m pre-rounded

        dim3 g2(Dd / 64, MROWS / BM);   // 520 blocks
        gemm_tc<0,true,64,false><<<g2, 256, SM64>>>(m, w2, b2, r, tok, MROWS, Dd, MLP_HID);
    }

    // 3. head1: (256, 16640) @ (16640, 8192), silu — A pre-rounded via round_kernel
    round_kernel<<<EW_GRID, 256>>>(tok, h);
    dim3 gh(HEAD_HID / 64, Bsz / BM);
    gemm_tc<2,false,64,false><<<gh, 256, SM64>>>(h, head1_w, head1_b, nullptr, hidden,
                                                 Bsz, HEAD_HID, T1 * Dd);

    // 4. head2: (256, 8192) @ (8192, 10)
    head2_kernel<<<Bsz, 256>>>(hidden, head2_w, head2_b, outp);
}